// round 1
// baseline (speedup 1.0000x reference)
#include <cuda_runtime.h>
#include <math_constants.h>

#define BATCH 4
#define CDIM  128
#define LDIM  4096
#define BM    64
#define BN    64

// Scratch for the kv_mapper output (keys == values), in two layouts.
__device__ float g_V_l[BATCH * LDIM * CDIM];  // [b][l][c]
__device__ float g_V_c[BATCH * CDIM * LDIM];  // [b][c][l]

// ---------------------------------------------------------------------------
// Prep: V[b,o,l] = sum_c W[o,c] * x[b,c,l] + bias[o]
// One CTA per (batch, 64-wide l tile). 256 threads (16x16).
// ---------------------------------------------------------------------------
__global__ void __launch_bounds__(256) prep_kernel(const float* __restrict__ x,
                                                   const float* __restrict__ W,
                                                   const float* __restrict__ bias) {
    extern __shared__ float sm[];
    float* Wt = sm;               // [c][o]  128 x 132
    float* xs = sm + 128 * 132;   // [c][l]  128 x 66   (reused as [o][l] later)

    const int b  = blockIdx.y;
    const int l0 = blockIdx.x * BM;
    const int tx = threadIdx.x, ty = threadIdx.y;
    const int tid = ty * 16 + tx;

    // Load W transposed: Wt[c][o] = W[o][c]
    for (int idx = tid; idx < 128 * 128; idx += 256) {
        int o = idx >> 7, c = idx & 127;
        Wt[c * 132 + o] = W[idx];
    }
    // Load x tile: xs[c][il] = x[b][c][l0+il]
    const float* xb = x + (b * CDIM) * LDIM + l0;
    for (int idx = tid; idx < 128 * 64; idx += 256) {
        int c = idx >> 6, il = idx & 63;
        xs[c * 66 + il] = xb[c * LDIM + il];
    }
    __syncthreads();

    // Each thread: 4 rows (l) x 8 cols (o)
    float acc[4][8];
#pragma unroll
    for (int i = 0; i < 4; i++)
#pragma unroll
        for (int j = 0; j < 8; j++) acc[i][j] = 0.0f;

#pragma unroll 4
    for (int c = 0; c < 128; c++) {
        float a[4];
#pragma unroll
        for (int i = 0; i < 4; i++) a[i] = xs[c * 66 + ty * 4 + i];
        float4 b0 = *(const float4*)&Wt[c * 132 + tx * 8];
        float4 b1 = *(const float4*)&Wt[c * 132 + tx * 8 + 4];
        float bb[8] = {b0.x, b0.y, b0.z, b0.w, b1.x, b1.y, b1.z, b1.w};
#pragma unroll
        for (int i = 0; i < 4; i++)
#pragma unroll
            for (int j = 0; j < 8; j++) acc[i][j] += a[i] * bb[j];
    }
    // Bias
#pragma unroll
    for (int j = 0; j < 8; j++) {
        float bj = bias[tx * 8 + j];
#pragma unroll
        for (int i = 0; i < 4; i++) acc[i][j] += bj;
    }

    // Write l-major layout: g_V_l[b][l][o]
#pragma unroll
    for (int i = 0; i < 4; i++) {
        int l = l0 + ty * 4 + i;
        float* dst = &g_V_l[(b * LDIM + l) * CDIM + tx * 8];
        *(float4*)(dst)     = make_float4(acc[i][0], acc[i][1], acc[i][2], acc[i][3]);
        *(float4*)(dst + 4) = make_float4(acc[i][4], acc[i][5], acc[i][6], acc[i][7]);
    }

    // Stage transpose to write c-major layout coalesced over l
    __syncthreads();
#pragma unroll
    for (int i = 0; i < 4; i++)
#pragma unroll
        for (int j = 0; j < 8; j++) xs[(tx * 8 + j) * 66 + ty * 4 + i] = acc[i][j];
    __syncthreads();
    for (int idx = tid; idx < 128 * 64; idx += 256) {
        int o = idx >> 6, il = idx & 63;
        g_V_c[(b * CDIM + o) * LDIM + l0 + il] = xs[o * 66 + il];
    }
}

// ---------------------------------------------------------------------------
// Flash attention, fp32 SIMT.
// One CTA per (batch, 64-query-row tile). 256 threads (16x16).
//   Qs[c][m] 128x68 c-major, Ks[c][n] 128x68 c-major,
//   Vs[t][c] 64x132 t-major, Ps[r][t] 64x68.
// Thread tiles: S-phase 4(m) x 4(n); O-phase 4(m) x 8(c).
// ---------------------------------------------------------------------------
__global__ void __launch_bounds__(256) attn_kernel(const float* __restrict__ x,
                                                   float* __restrict__ out) {
    extern __shared__ float sm[];
    float* Qs = sm;                      // 128*68
    float* Ks = Qs + 128 * 68;           // 128*68
    float* Vs = Ks + 128 * 68;           // 64*132
    float* Ps = Vs + 64 * 132;           // 64*68

    const int b  = blockIdx.y;
    const int m0 = blockIdx.x * BM;
    const int tx = threadIdx.x, ty = threadIdx.y;
    const int tid = ty * 16 + tx;
    const float scale = 0.08838834764831845f;  // 1/sqrt(128)

    // Load Q tile: Qs[c][m] = x[b][c][m0+m]  (coalesced over m, conflict-free store)
    const float* xb = x + (b * CDIM) * LDIM + m0;
    for (int idx = tid; idx < 128 * 64; idx += 256) {
        int c = idx >> 6, m = idx & 63;
        Qs[c * 68 + m] = xb[c * LDIM + m];
    }

    float O[4][8];
#pragma unroll
    for (int i = 0; i < 4; i++)
#pragma unroll
        for (int j = 0; j < 8; j++) O[i][j] = 0.0f;
    float mrow[4] = {-CUDART_INF_F, -CUDART_INF_F, -CUDART_INF_F, -CUDART_INF_F};
    float ssum[4] = {0.f, 0.f, 0.f, 0.f};

    for (int n0 = 0; n0 < LDIM; n0 += BN) {
        __syncthreads();  // previous iter reads done (covers Q staging on iter 0)

        // K tile c-major (conflict-free: coalesced read, contiguous store)
        const float* kvc = &g_V_c[b * CDIM * LDIM + n0];
        for (int idx = tid; idx < 128 * 64; idx += 256) {
            int c = idx >> 6, n = idx & 63;
            Ks[c * 68 + n] = kvc[c * LDIM + n];
        }
        // V tile t-major
        const float* kvl = &g_V_l[(b * LDIM + n0) * CDIM];
        for (int idx = tid; idx < 64 * 128; idx += 256) {
            int t = idx >> 7, c = idx & 127;
            Vs[t * 132 + c] = kvl[t * CDIM + c];
        }
        __syncthreads();

        // ---- S = Q . K^T  (rows m = ty*4+i, cols n = tx*4+j)
        float s[4][4];
#pragma unroll
        for (int i = 0; i < 4; i++)
#pragma unroll
            for (int j = 0; j < 4; j++) s[i][j] = 0.0f;

#pragma unroll 4
        for (int c = 0; c < 128; c++) {
            float4 a = *(const float4*)&Qs[c * 68 + (ty << 2)];
            float4 k = *(const float4*)&Ks[c * 68 + (tx << 2)];
            float av[4] = {a.x, a.y, a.z, a.w};
            float kv[4] = {k.x, k.y, k.z, k.w};
#pragma unroll
            for (int i = 0; i < 4; i++)
#pragma unroll
                for (int j = 0; j < 4; j++) s[i][j] += av[i] * kv[j];
        }

        // ---- online softmax per row (16 tx lanes own one row's 64 cols)
#pragma unroll
        for (int i = 0; i < 4; i++) {
            float rm = fmaxf(fmaxf(s[i][0], s[i][1]), fmaxf(s[i][2], s[i][3]));
#pragma unroll
            for (int off = 8; off > 0; off >>= 1)
                rm = fmaxf(rm, __shfl_xor_sync(0xFFFFFFFFu, rm, off));
            rm *= scale;
            float mnew  = fmaxf(mrow[i], rm);
            float alpha = __expf(mrow[i] - mnew);
            mrow[i] = mnew;

            float psum = 0.0f;
#pragma unroll
            for (int j = 0; j < 4; j++) {
                float p = __expf(s[i][j] * scale - mnew);
                Ps[(ty * 4 + i) * 68 + tx * 4 + j] = p;
                psum += p;
            }
#pragma unroll
            for (int off = 8; off > 0; off >>= 1)
                psum += __shfl_xor_sync(0xFFFFFFFFu, psum, off);
            ssum[i] = ssum[i] * alpha + psum;
#pragma unroll
            for (int j = 0; j < 8; j++) O[i][j] *= alpha;
        }
        __syncthreads();

        // ---- O += P . V   (rows m = ty*4+i, cols c = tx*8+j)
#pragma unroll 2
        for (int t = 0; t < 64; t++) {
            float4 v0 = *(const float4*)&Vs[t * 132 + (tx << 3)];
            float4 v1 = *(const float4*)&Vs[t * 132 + (tx << 3) + 4];
            float vv[8] = {v0.x, v0.y, v0.z, v0.w, v1.x, v1.y, v1.z, v1.w};
#pragma unroll
            for (int i = 0; i < 4; i++) {
                float p = Ps[(ty * 4 + i) * 68 + t];
#pragma unroll
                for (int j = 0; j < 8; j++) O[i][j] += p * vv[j];
            }
        }
    }

    // Normalize and write out[b][c][l] via smem transpose (coalesced over l).
    float inv[4];
#pragma unroll
    for (int i = 0; i < 4; i++) inv[i] = 1.0f / ssum[i];

    __syncthreads();  // done reading Qs (S-phase of last tile)
#pragma unroll
    for (int i = 0; i < 4; i++)
#pragma unroll
        for (int j = 0; j < 8; j++)
            Qs[(tx * 8 + j) * 68 + (ty * 4 + i)] = O[i][j] * inv[i];
    __syncthreads();

    float* ob = out + (b * CDIM) * LDIM + m0;
    for (int idx = tid; idx < 128 * 64; idx += 256) {
        int c = idx >> 6, m = idx & 63;
        ob[c * LDIM + m] = Qs[c * 68 + m];
    }
}

// ---------------------------------------------------------------------------
extern "C" void kernel_launch(void* const* d_in, const int* in_sizes, int n_in,
                              void* d_out, int out_size) {
    const float* x    = (const float*)d_in[0];
    const float* W_kv = (const float*)d_in[1];
    const float* b_kv = (const float*)d_in[2];
    float* out = (float*)d_out;

    const int prep_smem = (128 * 132 + 128 * 66) * (int)sizeof(float);   // 101376
    const int attn_smem = (128 * 68 * 2 + 64 * 132 + 64 * 68) * (int)sizeof(float);  // 120832

    cudaFuncSetAttribute(prep_kernel, cudaFuncAttributeMaxDynamicSharedMemorySize, prep_smem);
    cudaFuncSetAttribute(attn_kernel, cudaFuncAttributeMaxDynamicSharedMemorySize, attn_smem);

    dim3 block(16, 16);
    dim3 grid(LDIM / BM, BATCH);

    prep_kernel<<<grid, block, prep_smem>>>(x, W_kv, b_kv);
    attn_kernel<<<grid, block, attn_smem>>>(x, out);

    (void)in_sizes; (void)n_in; (void)out_size;
}